// round 6
// baseline (speedup 1.0000x reference)
#include <cuda_runtime.h>
#include <cuda_bf16.h>
#include <cstdint>
#include <math.h>

// Problem constants
#define B_ 8
#define T_ 8192
#define C_ 256
#define H_ 8
#define G_ 64
#define D_ 32
#define N_ (B_*T_)
#define NCH2 16
#define ASTR 40   // smem tile row stride in bf16 elems (80B, conflict-free for ldmatrix)

// ---------------- scratch ------------------------------------------------------
__device__ float g_tmp[(size_t)N_ * C_];
__device__ float g_sw[(size_t)N_ * H_ * G_];
__device__ __nv_bfloat16 g_swhi[(size_t)N_ * H_ * G_];
__device__ __nv_bfloat16 g_swlo[(size_t)N_ * H_ * G_];
__device__ float g_part[(size_t)B_ * H_ * NCH2 * G_ * D_];
__device__ float g_pnorm[(size_t)B_ * H_ * NCH2 * G_];
__device__ float g_os[(size_t)B_ * H_ * G_ * D_];
__device__ __nv_bfloat16 g_Whi[(size_t)C_ * C_];
__device__ __nv_bfloat16 g_Wlo[(size_t)C_ * C_];
__device__ __nv_bfloat16 g_Mhi[(size_t)B_ * C_ * (H_ * G_)];
__device__ __nv_bfloat16 g_Mlo[(size_t)B_ * C_ * (H_ * G_)];

// ---------------- small helpers ------------------------------------------------
__device__ __forceinline__ float2 ffma2(float2 a, float2 b, float2 c) {
    float2 d;
    asm("fma.rn.f32x2 %0, %1, %2, %3;"
        : "=l"(reinterpret_cast<unsigned long long&>(d))
        : "l"(reinterpret_cast<unsigned long long&>(a)),
          "l"(reinterpret_cast<unsigned long long&>(b)),
          "l"(reinterpret_cast<unsigned long long&>(c)));
    return d;
}
__device__ __forceinline__ uint32_t smem_to_u32(const void* p) {
    uint32_t a;
    asm("{ .reg .u64 t; cvta.to.shared.u64 t, %1; cvt.u32.u64 %0, t; }" : "=r"(a) : "l"(p));
    return a;
}
__device__ __forceinline__ void ldsm_x4(uint32_t& r0, uint32_t& r1, uint32_t& r2, uint32_t& r3,
                                        uint32_t addr) {
    asm volatile("ldmatrix.sync.aligned.m8n8.x4.shared.b16 {%0,%1,%2,%3}, [%4];"
                 : "=r"(r0), "=r"(r1), "=r"(r2), "=r"(r3) : "r"(addr));
}
__device__ __forceinline__ void mma_bf16(float* d, const uint32_t* a, uint32_t b0, uint32_t b1) {
    asm volatile("mma.sync.aligned.m16n8k16.row.col.f32.bf16.bf16.f32 "
        "{%0,%1,%2,%3}, {%4,%5,%6,%7}, {%8,%9}, {%0,%1,%2,%3};"
        : "+f"(d[0]), "+f"(d[1]), "+f"(d[2]), "+f"(d[3])
        : "r"(a[0]), "r"(a[1]), "r"(a[2]), "r"(a[3]), "r"(b0), "r"(b1));
}
__device__ __forceinline__ uint32_t bits2(__nv_bfloat162 h) {
    return *reinterpret_cast<uint32_t*>(&h);
}
#define CP_ASYNC16(dst, src) \
    asm volatile("cp.async.cg.shared.global [%0], [%1], 16;" :: "r"(dst), "l"(src))
#define CP_COMMIT() asm volatile("cp.async.commit_group;" ::: "memory")
#define CP_WAIT0()  asm volatile("cp.async.wait_group 0;" ::: "memory")

#define STG_BYTES (128 * ASTR * 2)            // one buffer: 10240 B
#define STAGE_BYTES (4 * STG_BYTES)           // Ahi,Alo,Bhi,Blo: 40960 B
#define GEMM_SMEM (2 * STAGE_BYTES)           // 81920 B
#define OAH 0
#define OAL STG_BYTES
#define OBH (2 * STG_BYTES)
#define OBL (3 * STG_BYTES)

// ============== GEMM variant 1: A fp32 (convert in-kernel), B pre-split ========
__global__ __launch_bounds__(256, 1) void hmma_gemm_kernel(
    const float* __restrict__ A, int lda, size_t strideA,
    const __nv_bfloat16* __restrict__ Bhi, const __nv_bfloat16* __restrict__ Blo,
    size_t strideB,
    float* __restrict__ Cm, int ldc, size_t strideC,
    const float* __restrict__ bias, int K)
{
    extern __shared__ __align__(16) char smd[];
    const uint32_t sbase = smem_to_u32(smd);

    const int tid = threadIdx.x;
    const int wid = tid >> 5, lane = tid & 31;
    const int wm = wid & 3, wn = wid >> 2;
    const int m0 = wm * 32, n0w = wn * 64;

    const float* Ab = A + (size_t)blockIdx.z * strideA + (size_t)blockIdx.y * 128 * lda;
    const __nv_bfloat16* Bhb = Bhi + (size_t)blockIdx.z * strideB + (size_t)(blockIdx.x * 128) * K;
    const __nv_bfloat16* Blb = Blo + (size_t)blockIdx.z * strideB + (size_t)(blockIdx.x * 128) * K;
    float* Cb = Cm + (size_t)blockIdx.z * strideC;

    const int lrow = lane & 15;
    const int lcol = (lane >> 4) * 8;
    const int arow = tid >> 1;
    const int akh  = (tid & 1) << 4;
    const int c0row = tid >> 1, c0seg = (tid & 1) * 2;

    float acc[2][8][4];
    #pragma unroll
    for (int mi = 0; mi < 2; mi++)
        #pragma unroll
        for (int n = 0; n < 8; n++)
            #pragma unroll
            for (int q = 0; q < 4; q++) acc[mi][n][q] = 0.f;

    float fst[16];

    auto load_A_regs = [&](int kt) {
        const float* ap = Ab + (size_t)arow * lda + kt + akh;
        *(float4*)(fst + 0)  = *(const float4*)(ap);
        *(float4*)(fst + 4)  = *(const float4*)(ap + 4);
        *(float4*)(fst + 8)  = *(const float4*)(ap + 8);
        *(float4*)(fst + 12) = *(const float4*)(ap + 12);
    };
    auto cpasync_B = [&](int kt, int stg) {
        uint32_t dst = sbase + stg * STAGE_BYTES + c0row * (ASTR * 2) + c0seg * 16;
        const char* srch = (const char*)(Bhb + (size_t)c0row * K + kt) + c0seg * 16;
        const char* srcl = (const char*)(Blb + (size_t)c0row * K + kt) + c0seg * 16;
        CP_ASYNC16(dst + OBH, srch);
        CP_ASYNC16(dst + OBH + 16, srch + 16);
        CP_ASYNC16(dst + OBL, srcl);
        CP_ASYNC16(dst + OBL + 16, srcl + 16);
    };
    auto store_A = [&](int stg) {
        uint32_t h[8], l[8];
        #pragma unroll
        for (int i = 0; i < 8; i++) {
            __nv_bfloat162 hb = __floats2bfloat162_rn(fst[2*i], fst[2*i+1]);
            float r0 = fst[2*i]   - __bfloat162float(hb.x);
            float r1 = fst[2*i+1] - __bfloat162float(hb.y);
            h[i] = bits2(hb);
            l[i] = bits2(__floats2bfloat162_rn(r0, r1));
        }
        char* dh = smd + stg * STAGE_BYTES + OAH + arow * (ASTR * 2) + akh * 2;
        char* dl = smd + stg * STAGE_BYTES + OAL + arow * (ASTR * 2) + akh * 2;
        ((uint4*)dh)[0] = make_uint4(h[0], h[1], h[2], h[3]);
        ((uint4*)dh)[1] = make_uint4(h[4], h[5], h[6], h[7]);
        ((uint4*)dl)[0] = make_uint4(l[0], l[1], l[2], l[3]);
        ((uint4*)dl)[1] = make_uint4(l[4], l[5], l[6], l[7]);
    };

    load_A_regs(0);
    cpasync_B(0, 0);
    CP_COMMIT();
    store_A(0);
    CP_WAIT0();
    __syncthreads();

    int stage = 0;
    for (int kt = 0; kt < K; kt += 32) {
        const bool has_next = (kt + 32 < K);
        if (has_next) {
            load_A_regs(kt + 32);
            cpasync_B(kt + 32, stage ^ 1);
            CP_COMMIT();
        }

        const uint32_t sb = sbase + stage * STAGE_BYTES;
        #pragma unroll
        for (int ks = 0; ks < 2; ks++) {
            const int cb = ks * 16 + lcol;
            uint32_t ahi[2][4], alo[2][4], bh[4][4], bl[4][4];
            #pragma unroll
            for (int mi = 0; mi < 2; mi++) {
                uint32_t off = ((m0 + mi * 16 + lrow) * ASTR + cb) * 2;
                ldsm_x4(ahi[mi][0], ahi[mi][1], ahi[mi][2], ahi[mi][3], sb + OAH + off);
                ldsm_x4(alo[mi][0], alo[mi][1], alo[mi][2], alo[mi][3], sb + OAL + off);
            }
            #pragma unroll
            for (int nj = 0; nj < 4; nj++) {
                uint32_t off = ((n0w + nj * 16 + lrow) * ASTR + cb) * 2;
                ldsm_x4(bh[nj][0], bh[nj][1], bh[nj][2], bh[nj][3], sb + OBH + off);
                ldsm_x4(bl[nj][0], bl[nj][1], bl[nj][2], bl[nj][3], sb + OBL + off);
            }
            #pragma unroll
            for (int mi = 0; mi < 2; mi++) {
                #pragma unroll
                for (int nj = 0; nj < 4; nj++) {
                    float* d0 = acc[mi][nj * 2];
                    mma_bf16(d0, ahi[mi], bh[nj][0], bh[nj][2]);
                    mma_bf16(d0, ahi[mi], bl[nj][0], bl[nj][2]);
                    mma_bf16(d0, alo[mi], bh[nj][0], bh[nj][2]);
                    float* d1 = acc[mi][nj * 2 + 1];
                    mma_bf16(d1, ahi[mi], bh[nj][1], bh[nj][3]);
                    mma_bf16(d1, ahi[mi], bl[nj][1], bl[nj][3]);
                    mma_bf16(d1, alo[mi], bh[nj][1], bh[nj][3]);
                }
            }
        }

        if (has_next) {
            store_A(stage ^ 1);
            CP_WAIT0();
            __syncthreads();
            stage ^= 1;
        }
    }

    const int grp = lane >> 2, qid = lane & 3;
    #pragma unroll
    for (int mi = 0; mi < 2; mi++) {
        #pragma unroll
        for (int nj = 0; nj < 8; nj++) {
            int row = blockIdx.y * 128 + m0 + mi * 16 + grp;
            int col = blockIdx.x * 128 + n0w + nj * 8 + qid * 2;
            float b0 = bias[col], b1 = bias[col + 1];
            *(float2*)(Cb + (size_t)row * ldc + col) =
                make_float2(acc[mi][nj][0] + b0, acc[mi][nj][1] + b1);
            *(float2*)(Cb + (size_t)(row + 8) * ldc + col) =
                make_float2(acc[mi][nj][2] + b0, acc[mi][nj][3] + b1);
        }
    }
}

// ============== GEMM variant 2: BOTH operands pre-split bf16, all cp.async =====
__global__ __launch_bounds__(256, 2) void hmma_gemm_ab_kernel(
    const __nv_bfloat16* __restrict__ Ahi, const __nv_bfloat16* __restrict__ Alo,
    size_t strideA,
    const __nv_bfloat16* __restrict__ Bhi, const __nv_bfloat16* __restrict__ Blo,
    size_t strideB,
    float* __restrict__ Cm, int ldc, size_t strideC,
    const float* __restrict__ bias, int K)
{
    extern __shared__ __align__(16) char smd[];
    const uint32_t sbase = smem_to_u32(smd);

    const int tid = threadIdx.x;
    const int wid = tid >> 5, lane = tid & 31;
    const int wm = wid & 3, wn = wid >> 2;
    const int m0 = wm * 32, n0w = wn * 64;

    const __nv_bfloat16* Ahb = Ahi + (size_t)blockIdx.z * strideA + (size_t)(blockIdx.y * 128) * K;
    const __nv_bfloat16* Alb = Alo + (size_t)blockIdx.z * strideA + (size_t)(blockIdx.y * 128) * K;
    const __nv_bfloat16* Bhb = Bhi + (size_t)blockIdx.z * strideB + (size_t)(blockIdx.x * 128) * K;
    const __nv_bfloat16* Blb = Blo + (size_t)blockIdx.z * strideB + (size_t)(blockIdx.x * 128) * K;
    float* Cb = Cm + (size_t)blockIdx.z * strideC;

    const int lrow = lane & 15;
    const int lcol = (lane >> 4) * 8;
    const int c0row = tid >> 1, c0seg = (tid & 1) * 2;

    float acc[2][8][4];
    #pragma unroll
    for (int mi = 0; mi < 2; mi++)
        #pragma unroll
        for (int n = 0; n < 8; n++)
            #pragma unroll
            for (int q = 0; q < 4; q++) acc[mi][n][q] = 0.f;

    auto cpasync_all = [&](int kt, int stg) {
        uint32_t dst = sbase + stg * STAGE_BYTES + c0row * (ASTR * 2) + c0seg * 16;
        const char* sah = (const char*)(Ahb + (size_t)c0row * K + kt) + c0seg * 16;
        const char* sal = (const char*)(Alb + (size_t)c0row * K + kt) + c0seg * 16;
        const char* sbh = (const char*)(Bhb + (size_t)c0row * K + kt) + c0seg * 16;
        const char* sbl = (const char*)(Blb + (size_t)c0row * K + kt) + c0seg * 16;
        CP_ASYNC16(dst + OAH, sah); CP_ASYNC16(dst + OAH + 16, sah + 16);
        CP_ASYNC16(dst + OAL, sal); CP_ASYNC16(dst + OAL + 16, sal + 16);
        CP_ASYNC16(dst + OBH, sbh); CP_ASYNC16(dst + OBH + 16, sbh + 16);
        CP_ASYNC16(dst + OBL, sbl); CP_ASYNC16(dst + OBL + 16, sbl + 16);
    };

    cpasync_all(0, 0);
    CP_COMMIT();
    CP_WAIT0();
    __syncthreads();

    int stage = 0;
    for (int kt = 0; kt < K; kt += 32) {
        const bool has_next = (kt + 32 < K);
        if (has_next) {
            cpasync_all(kt + 32, stage ^ 1);
            CP_COMMIT();
        }

        const uint32_t sb = sbase + stage * STAGE_BYTES;
        #pragma unroll
        for (int ks = 0; ks < 2; ks++) {
            const int cb = ks * 16 + lcol;
            uint32_t ahi[2][4], alo[2][4], bh[4][4], bl[4][4];
            #pragma unroll
            for (int mi = 0; mi < 2; mi++) {
                uint32_t off = ((m0 + mi * 16 + lrow) * ASTR + cb) * 2;
                ldsm_x4(ahi[mi][0], ahi[mi][1], ahi[mi][2], ahi[mi][3], sb + OAH + off);
                ldsm_x4(alo[mi][0], alo[mi][1], alo[mi][2], alo[mi][3], sb + OAL + off);
            }
            #pragma unroll
            for (int nj = 0; nj < 4; nj++) {
                uint32_t off = ((n0w + nj * 16 + lrow) * ASTR + cb) * 2;
                ldsm_x4(bh[nj][0], bh[nj][1], bh[nj][2], bh[nj][3], sb + OBH + off);
                ldsm_x4(bl[nj][0], bl[nj][1], bl[nj][2], bl[nj][3], sb + OBL + off);
            }
            #pragma unroll
            for (int mi = 0; mi < 2; mi++) {
                #pragma unroll
                for (int nj = 0; nj < 4; nj++) {
                    float* d0 = acc[mi][nj * 2];
                    mma_bf16(d0, ahi[mi], bh[nj][0], bh[nj][2]);
                    mma_bf16(d0, ahi[mi], bl[nj][0], bl[nj][2]);
                    mma_bf16(d0, alo[mi], bh[nj][0], bh[nj][2]);
                    float* d1 = acc[mi][nj * 2 + 1];
                    mma_bf16(d1, ahi[mi], bh[nj][1], bh[nj][3]);
                    mma_bf16(d1, ahi[mi], bl[nj][1], bl[nj][3]);
                    mma_bf16(d1, alo[mi], bh[nj][1], bh[nj][3]);
                }
            }
        }

        if (has_next) {
            CP_WAIT0();
            __syncthreads();
            stage ^= 1;
        }
    }

    const int grp = lane >> 2, qid = lane & 3;
    #pragma unroll
    for (int mi = 0; mi < 2; mi++) {
        #pragma unroll
        for (int nj = 0; nj < 8; nj++) {
            int row = blockIdx.y * 128 + m0 + mi * 16 + grp;
            int col = blockIdx.x * 128 + n0w + nj * 8 + qid * 2;
            float b0 = bias[col], b1 = bias[col + 1];
            *(float2*)(Cb + (size_t)row * ldc + col) =
                make_float2(acc[mi][nj][0] + b0, acc[mi][nj][1] + b1);
            *(float2*)(Cb + (size_t)(row + 8) * ldc + col) =
                make_float2(acc[mi][nj][2] + b0, acc[mi][nj][3] + b1);
        }
    }
}

// ---------------- prep: split W_in into transposed bf16 hi/lo ------------------
__global__ __launch_bounds__(256) void split_w_kernel(const float* __restrict__ W)
{
    int idx = blockIdx.x * 256 + threadIdx.x;   // k*256 + n
    int k = idx >> 8, n = idx & 255;
    float v = W[idx];
    __nv_bfloat16 h = __float2bfloat16_rn(v);
    g_Whi[(size_t)n * C_ + k] = h;
    g_Wlo[(size_t)n * C_ + k] = __float2bfloat16_rn(v - __bfloat162float(h));
}

// ---------------- K2: slice weights + pre-split bf16 emit ----------------------
__global__ __launch_bounds__(256) void slicew_kernel(
    const float* __restrict__ Wslice, const float* __restrict__ bslice,
    const float* __restrict__ temp)
{
    __shared__ float Ws[D_ * G_];
    __shared__ float bs[G_];
    __shared__ float it[H_];
    int tid = threadIdx.x;
    #pragma unroll
    for (int i = 0; i < 8; i++) Ws[tid + i * 256] = Wslice[tid + i * 256];
    if (tid < G_) bs[tid] = bslice[tid];
    if (tid < H_) it[tid] = 1.f / temp[tid];
    __syncthreads();

    int gid = blockIdx.x * 256 + tid;
    int n = gid >> 3, h = gid & 7;

    float x[D_];
    const float4* xr = (const float4*)(g_tmp + (size_t)n * C_ + h * D_);
    #pragma unroll
    for (int i = 0; i < 8; i++) {
        float4 v = xr[i];
        x[4*i] = v.x; x[4*i+1] = v.y; x[4*i+2] = v.z; x[4*i+3] = v.w;
    }

    float2 lg[G_ / 2];
    const float2* bs2 = (const float2*)bs;
    #pragma unroll
    for (int j = 0; j < G_ / 2; j++) lg[j] = bs2[j];

    const float2* Ws2 = (const float2*)Ws;
    for (int d = 0; d < D_; d++) {
        float2 xv = make_float2(x[d], x[d]);
        #pragma unroll
        for (int j = 0; j < G_ / 2; j++) lg[j] = ffma2(xv, Ws2[d * (G_ / 2) + j], lg[j]);
    }

    float sc = it[h];
    float mx = -1e30f;
    #pragma unroll
    for (int j = 0; j < G_ / 2; j++) {
        lg[j].x *= sc; lg[j].y *= sc;
        mx = fmaxf(mx, fmaxf(lg[j].x, lg[j].y));
    }
    float sum = 0.f;
    #pragma unroll
    for (int j = 0; j < G_ / 2; j++) {
        lg[j].x = __expf(lg[j].x - mx);
        lg[j].y = __expf(lg[j].y - mx);
        sum += lg[j].x + lg[j].y;
    }
    float inv = 1.f / sum;

    size_t base = (size_t)n * (H_ * G_) + h * G_;
    float4* dst = (float4*)(g_sw + base);
    uint2* dhi = (uint2*)(g_swhi + base);
    uint2* dlo = (uint2*)(g_swlo + base);
    #pragma unroll
    for (int j = 0; j < 16; j++) {
        float v0 = lg[2*j].x * inv, v1 = lg[2*j].y * inv;
        float v2 = lg[2*j+1].x * inv, v3 = lg[2*j+1].y * inv;
        dst[j] = make_float4(v0, v1, v2, v3);
        __nv_bfloat162 h01 = __floats2bfloat162_rn(v0, v1);
        __nv_bfloat162 h23 = __floats2bfloat162_rn(v2, v3);
        dhi[j] = make_uint2(bits2(h01), bits2(h23));
        __nv_bfloat162 l01 = __floats2bfloat162_rn(v0 - __bfloat162float(h01.x),
                                                   v1 - __bfloat162float(h01.y));
        __nv_bfloat162 l23 = __floats2bfloat162_rn(v2 - __bfloat162float(h23.x),
                                                   v3 - __bfloat162float(h23.y));
        dlo[j] = make_uint2(bits2(l01), bits2(l23));
    }
}

// ---------------- K3: pooling, register-accumulated ----------------------------
// grid (NCH2, B*H), block 256. Warp = (g-half, row-quarter).
// Each thread: lane = d, accumulates 32 g in 16 float2 regs over 512 rows.
__global__ __launch_bounds__(256) void pool_kernel()
{
    __shared__ float sm[12288];            // xs 4096 | sws 8192; reused for reduce
    float* xs  = sm;                       // [128][32]
    float* sws = sm + 4096;                // [128][64]

    int pc = blockIdx.x, bh = blockIdx.y;
    int b = bh >> 3, h = bh & 7;
    int tid = threadIdx.x;
    int lane = tid & 31, w = tid >> 5;
    int gh = w >> 2, rq = w & 3;
    int gbase = gh * 32;

    float2 acc[16];
    #pragma unroll
    for (int j = 0; j < 16; j++) acc[j] = make_float2(0.f, 0.f);
    float nacc = 0.f;

    for (int sc = 0; sc < 4; sc++) {
        size_t nbase = (size_t)b * T_ + ((size_t)pc * 4 + sc) * 128;
        #pragma unroll
        for (int p = 0; p < 4; p++) {
            int r = (tid >> 3) + p * 32;
            ((float4*)(xs + r * 32))[tid & 7] =
                ((const float4*)(g_tmp + (nbase + r) * C_ + h * D_))[tid & 7];
        }
        #pragma unroll
        for (int p = 0; p < 8; p++) {
            int r = (tid >> 4) + p * 16;
            ((float4*)(sws + r * 64))[tid & 15] =
                ((const float4*)(g_sw + (nbase + r) * (H_ * G_) + h * G_))[tid & 15];
        }
        __syncthreads();

        #pragma unroll 2
        for (int r = 0; r < 32; r++) {
            int rr = rq * 32 + r;
            float xv = xs[rr * 32 + lane];
            const float4* wr = (const float4*)(sws + rr * 64 + gbase);
            float4 w0 = wr[0], w1 = wr[1], w2 = wr[2], w3 = wr[3];
            float2 xv2 = make_float2(xv, xv);
            acc[0]  = ffma2(xv2, make_float2(w0.x, w0.y), acc[0]);
            acc[1]  = ffma2(xv2, make_float2(w0.z, w0.w), acc[1]);
            acc[2]  = ffma2(xv2, make_float2(w1.x, w1.y), acc[2]);
            acc[3]  = ffma2(xv2, make_float2(w1.z, w1.w), acc[3]);
            acc[4]  = ffma2(xv2, make_float2(w2.x, w2.y), acc[4]);
            acc[5]  = ffma2(xv2, make_float2(w2.z, w2.w), acc[5]);
            acc[6]  = ffma2(xv2, make_float2(w3.x, w3.y), acc[6]);
            acc[7]  = ffma2(xv2, make_float2(w3.z, w3.w), acc[7]);
            const float4* wr2 = wr + 4;
            float4 w4 = wr2[0], w5 = wr2[1], w6 = wr2[2], w7 = wr2[3];
            acc[8]  = ffma2(xv2, make_float2(w4.x, w4.y), acc[8]);
            acc[9]  = ffma2(xv2, make_float2(w4.z, w4.w), acc[9]);
            acc[10] = ffma2(xv2, make_float2(w5.x, w5.y), acc[10]);
            acc[11] = ffma2(xv2, make_float2(w5.z, w5.w), acc[11]);
            acc[12] = ffma2(xv2, make_float2(w6.x, w6.y), acc[12]);
            acc[13] = ffma2(xv2, make_float2(w6.z, w6.w), acc[13]);
            acc[14] = ffma2(xv2, make_float2(w7.x, w7.y), acc[14]);
            acc[15] = ffma2(xv2, make_float2(w7.z, w7.w), acc[15]);
            nacc += sws[rr * 64 + gbase + lane];
        }
        __syncthreads();
    }

    // reduction across 4 row-quarter warps per g-half
    // red[w][glocal][slot], slot 0..31 = d, slot 32 = norm; stride 33
    float* red = sm;
    #pragma unroll
    for (int j = 0; j < 16; j++) {
        red[(w * 32 + 2 * j) * 33 + lane]     = acc[j].x;
        red[(w * 32 + 2 * j + 1) * 33 + lane] = acc[j].y;
    }
    red[(w * 32 + lane) * 33 + 32] = nacc;
    __syncthreads();

    size_t pbase = ((size_t)bh * NCH2 + pc) * (G_ * D_);
    size_t nbase2 = ((size_t)bh * NCH2 + pc) * G_;
    for (int idx = tid; idx < 64 * 33; idx += 256) {
        int g = idx / 33, s = idx - g * 33;
        int ghh = g >> 5, gl = g & 31;
        float sum = 0.f;
        #pragma unroll
        for (int r = 0; r < 4; r++)
            sum += red[((ghh * 4 + r) * 32 + gl) * 33 + s];
        if (s < 32) g_part[pbase + (size_t)g * D_ + s] = sum;
        else        g_pnorm[nbase2 + g] = sum;
    }
}

// ------- K4a: reduce partials -> tokens -> qkv -> GxG attention -> g_os --------
__global__ __launch_bounds__(256) void attn_tiny_kernel(
    const float* __restrict__ Wq, const float* __restrict__ bq,
    const float* __restrict__ Wk, const float* __restrict__ bk,
    const float* __restrict__ Wv, const float* __restrict__ bv)
{
    __shared__ float tok[G_][D_ + 1];
    __shared__ float qs[G_][D_ + 1];
    __shared__ float ks[G_][D_ + 1];
    __shared__ float vs[G_][D_ + 1];
    __shared__ float norms[G_];

    int bh = blockIdx.x;
    int tid = threadIdx.x;

    if (tid < G_) {
        float s = 0.f;
        for (int ch = 0; ch < NCH2; ch++)
            s += g_pnorm[((size_t)bh * NCH2 + ch) * G_ + tid];
        norms[tid] = s + 1e-5f;
    }
    __syncthreads();

    #pragma unroll
    for (int i = 0; i < 8; i++) {
        int c = tid + i * 256;
        int g = c >> 5, d = c & 31;
        float s = 0.f;
        for (int ch = 0; ch < NCH2; ch++)
            s += g_part[((size_t)bh * NCH2 + ch) * (G_ * D_) + c];
        tok[g][d] = s / norms[g];
    }
    __syncthreads();

    #pragma unroll
    for (int i = 0; i < 8; i++) {
        int c = tid + i * 256;
        int g = c >> 5, d = c & 31;
        float aq = bq[d], ak = bk[d], av = bv[d];
        for (int e = 0; e < D_; e++) {
            float t = tok[g][e];
            aq += t * Wq[e * D_ + d];
            ak += t * Wk[e * D_ + d];
            av += t * Wv[e * D_ + d];
        }
        qs[g][d] = aq; ks[g][d] = ak; vs[g][d] = av;
    }
    __syncthreads();

    if (tid < G_) {
        float qr[D_];
        #pragma unroll
        for (int d = 0; d < D_; d++) qr[d] = qs[tid][d];
        float s[G_];
        float mx = -1e30f;
        #pragma unroll
        for (int j = 0; j < G_; j++) {
            float a = 0.f;
            #pragma unroll
            for (int d = 0; d < D_; d++) a += qr[d] * ks[j][d];
            a *= 0.17677669529663687f;
            s[j] = a; mx = fmaxf(mx, a);
        }
        float sum = 0.f;
        #pragma unroll
        for (int j = 0; j < G_; j++) { s[j] = __expf(s[j] - mx); sum += s[j]; }
        float inv = 1.f / sum;
        #pragma unroll
        for (int d = 0; d < D_; d++) {
            float a = 0.f;
            #pragma unroll
            for (int j = 0; j < G_; j++) a += s[j] * vs[j][d];
            g_os[(size_t)bh * (G_ * D_) + tid * D_ + d] = a * inv;
        }
    }
}

// ------- K4b: fold into transposed bf16 hi/lo M --------------------------------
__global__ __launch_bounds__(256) void fold_kernel(const float* __restrict__ Wout)
{
    __shared__ float os[G_][D_ + 1];
    __shared__ float Wt[D_][G_ + 1];
    int bh = blockIdx.y;
    int b = bh >> 3, h = bh & 7;
    int col0 = blockIdx.x * 64;
    int tid = threadIdx.x;

    #pragma unroll
    for (int i = 0; i < 8; i++) {
        int idx = tid + i * 256;
        os[idx >> 5][idx & 31] = g_os[(size_t)bh * (G_ * D_) + idx];
    }
    #pragma unroll
    for (int i = 0; i < 8; i++) {
        int idx = tid + i * 256;
        int d = idx >> 6, c = idx & 63;
        Wt[d][c] = Wout[(size_t)(h * D_ + d) * C_ + col0 + c];
    }
    __syncthreads();

    int c = tid & 63, g0 = tid >> 6;
    #pragma unroll
    for (int gi = 0; gi < 16; gi++) {
        int g = g0 * 16 + gi;
        float a = 0.f;
        #pragma unroll
        for (int d = 0; d < D_; d++) a += os[g][d] * Wt[d][c];
        __nv_bfloat16 hb = __float2bfloat16_rn(a);
        size_t o = ((size_t)b * C_ + col0 + c) * (size_t)(H_ * G_) + h * G_ + g;
        g_Mhi[o] = hb;
        g_Mlo[o] = __float2bfloat16_rn(a - __bfloat162float(hb));
    }
}

// ---------------- launch --------------------------------------------------------
extern "C" void kernel_launch(void* const* d_in, const int* in_sizes, int n_in,
                              void* d_out, int out_size)
{
    const float* x_q    = (const float*)d_in[0];
    const float* W_in   = (const float*)d_in[3];
    const float* b_in   = (const float*)d_in[4];
    const float* W_sl   = (const float*)d_in[5];
    const float* b_sl   = (const float*)d_in[6];
    const float* temp   = (const float*)d_in[7];
    const float* W_q    = (const float*)d_in[8];
    const float* b_q    = (const float*)d_in[9];
    const float* W_k    = (const float*)d_in[10];
    const float* b_k    = (const float*)d_in[11];
    const float* W_v    = (const float*)d_in[12];
    const float* b_v    = (const float*)d_in[13];
    const float* W_out  = (const float*)d_in[14];
    const float* b_out  = (const float*)d_in[15];
    float* out = (float*)d_out;

    float *tmp_p;
    __nv_bfloat16 *whi_p, *wlo_p, *mhi_p, *mlo_p, *shi_p, *slo_p;
    cudaGetSymbolAddress((void**)&tmp_p, g_tmp);
    cudaGetSymbolAddress((void**)&whi_p, g_Whi);
    cudaGetSymbolAddress((void**)&wlo_p, g_Wlo);
    cudaGetSymbolAddress((void**)&mhi_p, g_Mhi);
    cudaGetSymbolAddress((void**)&mlo_p, g_Mlo);
    cudaGetSymbolAddress((void**)&shi_p, g_swhi);
    cudaGetSymbolAddress((void**)&slo_p, g_swlo);

    static int smem_set = 0;
    if (!smem_set) {
        cudaFuncSetAttribute(hmma_gemm_kernel,
                             cudaFuncAttributeMaxDynamicSharedMemorySize, GEMM_SMEM);
        cudaFuncSetAttribute(hmma_gemm_ab_kernel,
                             cudaFuncAttributeMaxDynamicSharedMemorySize, GEMM_SMEM);
        smem_set = 1;
    }

    // prep: split W_in
    split_w_kernel<<<C_ * C_ / 256, 256>>>(W_in);

    // K1: tmp = x_q @ W_in + b_in   (A fp32, convert in kernel)
    hmma_gemm_kernel<<<dim3(C_/128, N_/128, 1), 256, GEMM_SMEM>>>(
        x_q, C_, 0, whi_p, wlo_p, 0, tmp_p, C_, 0, b_in, C_);

    // K2: slice softmax (+ pre-split bf16 sw emit)
    slicew_kernel<<<(N_ * H_) / 256, 256>>>(W_sl, b_sl, temp);

    // K3: pooling partials (register-accumulated)
    pool_kernel<<<dim3(NCH2, B_ * H_), 256>>>();

    // K4a: reduce + tiny attention
    attn_tiny_kernel<<<B_ * H_, 256>>>(W_q, b_q, W_k, b_k, W_v, b_v);

    // K4b: fold W_out into pre-split M
    fold_kernel<<<dim3(4, B_ * H_), 256>>>(W_out);

    // K5: out[b] = SW[b] @ M[b] + b_out   (both operands pre-split, full cp.async)
    hmma_gemm_ab_kernel<<<dim3(C_/128, T_/128, B_), 256, GEMM_SMEM>>>(
        shi_p, slo_p, (size_t)T_ * (H_ * G_),
        mhi_p, mlo_p, (size_t)C_ * (H_ * G_),
        out, C_, (size_t)T_ * C_,
        b_out, H_ * G_);
}

// round 7
// speedup vs baseline: 1.0946x; 1.0946x over previous
#include <cuda_runtime.h>
#include <cuda_bf16.h>
#include <cstdint>
#include <math.h>

// Problem constants
#define B_ 8
#define T_ 8192
#define C_ 256
#define H_ 8
#define G_ 64
#define D_ 32
#define N_ (B_*T_)
#define NCH2 16
#define ASTR 40   // GEMM smem row stride (80B, conflict-free for ldmatrix)

// ---------------- scratch ------------------------------------------------------
__device__ float g_tmp[(size_t)N_ * C_];
__device__ __nv_bfloat16 g_swhi[(size_t)N_ * H_ * G_];
__device__ __nv_bfloat16 g_swlo[(size_t)N_ * H_ * G_];
__device__ float g_part[(size_t)B_ * H_ * NCH2 * G_ * D_];
__device__ float g_pnorm[(size_t)B_ * H_ * NCH2 * G_];
__device__ float g_os[(size_t)B_ * H_ * G_ * D_];
__device__ __nv_bfloat16 g_Whi[(size_t)C_ * C_];
__device__ __nv_bfloat16 g_Wlo[(size_t)C_ * C_];
__device__ __nv_bfloat16 g_Mhi[(size_t)B_ * C_ * (H_ * G_)];
__device__ __nv_bfloat16 g_Mlo[(size_t)B_ * C_ * (H_ * G_)];

// ---------------- small helpers ------------------------------------------------
__device__ __forceinline__ float2 ffma2(float2 a, float2 b, float2 c) {
    float2 d;
    asm("fma.rn.f32x2 %0, %1, %2, %3;"
        : "=l"(reinterpret_cast<unsigned long long&>(d))
        : "l"(reinterpret_cast<unsigned long long&>(a)),
          "l"(reinterpret_cast<unsigned long long&>(b)),
          "l"(reinterpret_cast<unsigned long long&>(c)));
    return d;
}
__device__ __forceinline__ uint32_t smem_to_u32(const void* p) {
    uint32_t a;
    asm("{ .reg .u64 t; cvta.to.shared.u64 t, %1; cvt.u32.u64 %0, t; }" : "=r"(a) : "l"(p));
    return a;
}
__device__ __forceinline__ void ldsm_x4(uint32_t& r0, uint32_t& r1, uint32_t& r2, uint32_t& r3,
                                        uint32_t addr) {
    asm volatile("ldmatrix.sync.aligned.m8n8.x4.shared.b16 {%0,%1,%2,%3}, [%4];"
                 : "=r"(r0), "=r"(r1), "=r"(r2), "=r"(r3) : "r"(addr));
}
__device__ __forceinline__ void stsm_x4_t(uint32_t addr, uint32_t r0, uint32_t r1,
                                          uint32_t r2, uint32_t r3) {
    asm volatile("stmatrix.sync.aligned.m8n8.x4.trans.shared.b16 [%0], {%1,%2,%3,%4};"
                 :: "r"(addr), "r"(r0), "r"(r1), "r"(r2), "r"(r3) : "memory");
}
__device__ __forceinline__ void mma_bf16(float* d, const uint32_t* a, uint32_t b0, uint32_t b1) {
    asm volatile("mma.sync.aligned.m16n8k16.row.col.f32.bf16.bf16.f32 "
        "{%0,%1,%2,%3}, {%4,%5,%6,%7}, {%8,%9}, {%0,%1,%2,%3};"
        : "+f"(d[0]), "+f"(d[1]), "+f"(d[2]), "+f"(d[3])
        : "r"(a[0]), "r"(a[1]), "r"(a[2]), "r"(a[3]), "r"(b0), "r"(b1));
}
__device__ __forceinline__ uint32_t bits2(__nv_bfloat162 h) {
    return *reinterpret_cast<uint32_t*>(&h);
}
#define CP_ASYNC16(dst, src) \
    asm volatile("cp.async.cg.shared.global [%0], [%1], 16;" :: "r"(dst), "l"(src))
#define CP_COMMIT() asm volatile("cp.async.commit_group;" ::: "memory")
#define CP_WAIT0()  asm volatile("cp.async.wait_group 0;" ::: "memory")

#define STG_BYTES (128 * ASTR * 2)
#define STAGE_BYTES (4 * STG_BYTES)
#define GEMM_SMEM (2 * STAGE_BYTES)
#define OAH 0
#define OAL STG_BYTES
#define OBH (2 * STG_BYTES)
#define OBL (3 * STG_BYTES)

// ============== GEMM variant 1: A fp32 (convert in-kernel), B pre-split ========
__global__ __launch_bounds__(256, 1) void hmma_gemm_kernel(
    const float* __restrict__ A, int lda, size_t strideA,
    const __nv_bfloat16* __restrict__ Bhi, const __nv_bfloat16* __restrict__ Blo,
    size_t strideB,
    float* __restrict__ Cm, int ldc, size_t strideC,
    const float* __restrict__ bias, int K)
{
    extern __shared__ __align__(16) char smd[];
    const uint32_t sbase = smem_to_u32(smd);

    const int tid = threadIdx.x;
    const int wid = tid >> 5, lane = tid & 31;
    const int wm = wid & 3, wn = wid >> 2;
    const int m0 = wm * 32, n0w = wn * 64;

    const float* Ab = A + (size_t)blockIdx.z * strideA + (size_t)blockIdx.y * 128 * lda;
    const __nv_bfloat16* Bhb = Bhi + (size_t)blockIdx.z * strideB + (size_t)(blockIdx.x * 128) * K;
    const __nv_bfloat16* Blb = Blo + (size_t)blockIdx.z * strideB + (size_t)(blockIdx.x * 128) * K;
    float* Cb = Cm + (size_t)blockIdx.z * strideC;

    const int lrow = lane & 15;
    const int lcol = (lane >> 4) * 8;
    const int arow = tid >> 1;
    const int akh  = (tid & 1) << 4;
    const int c0row = tid >> 1, c0seg = (tid & 1) * 2;

    float acc[2][8][4];
    #pragma unroll
    for (int mi = 0; mi < 2; mi++)
        #pragma unroll
        for (int n = 0; n < 8; n++)
            #pragma unroll
            for (int q = 0; q < 4; q++) acc[mi][n][q] = 0.f;

    float fst[16];

    auto load_A_regs = [&](int kt) {
        const float* ap = Ab + (size_t)arow * lda + kt + akh;
        *(float4*)(fst + 0)  = *(const float4*)(ap);
        *(float4*)(fst + 4)  = *(const float4*)(ap + 4);
        *(float4*)(fst + 8)  = *(const float4*)(ap + 8);
        *(float4*)(fst + 12) = *(const float4*)(ap + 12);
    };
    auto cpasync_B = [&](int kt, int stg) {
        uint32_t dst = sbase + stg * STAGE_BYTES + c0row * (ASTR * 2) + c0seg * 16;
        const char* srch = (const char*)(Bhb + (size_t)c0row * K + kt) + c0seg * 16;
        const char* srcl = (const char*)(Blb + (size_t)c0row * K + kt) + c0seg * 16;
        CP_ASYNC16(dst + OBH, srch);
        CP_ASYNC16(dst + OBH + 16, srch + 16);
        CP_ASYNC16(dst + OBL, srcl);
        CP_ASYNC16(dst + OBL + 16, srcl + 16);
    };
    auto store_A = [&](int stg) {
        uint32_t h[8], l[8];
        #pragma unroll
        for (int i = 0; i < 8; i++) {
            __nv_bfloat162 hb = __floats2bfloat162_rn(fst[2*i], fst[2*i+1]);
            float r0 = fst[2*i]   - __bfloat162float(hb.x);
            float r1 = fst[2*i+1] - __bfloat162float(hb.y);
            h[i] = bits2(hb);
            l[i] = bits2(__floats2bfloat162_rn(r0, r1));
        }
        char* dh = smd + stg * STAGE_BYTES + OAH + arow * (ASTR * 2) + akh * 2;
        char* dl = smd + stg * STAGE_BYTES + OAL + arow * (ASTR * 2) + akh * 2;
        ((uint4*)dh)[0] = make_uint4(h[0], h[1], h[2], h[3]);
        ((uint4*)dh)[1] = make_uint4(h[4], h[5], h[6], h[7]);
        ((uint4*)dl)[0] = make_uint4(l[0], l[1], l[2], l[3]);
        ((uint4*)dl)[1] = make_uint4(l[4], l[5], l[6], l[7]);
    };

    load_A_regs(0);
    cpasync_B(0, 0);
    CP_COMMIT();
    store_A(0);
    CP_WAIT0();
    __syncthreads();

    int stage = 0;
    for (int kt = 0; kt < K; kt += 32) {
        const bool has_next = (kt + 32 < K);
        if (has_next) {
            load_A_regs(kt + 32);
            cpasync_B(kt + 32, stage ^ 1);
            CP_COMMIT();
        }

        const uint32_t sb = sbase + stage * STAGE_BYTES;
        #pragma unroll
        for (int ks = 0; ks < 2; ks++) {
            const int cb = ks * 16 + lcol;
            uint32_t ahi[2][4], alo[2][4], bh[4][4], bl[4][4];
            #pragma unroll
            for (int mi = 0; mi < 2; mi++) {
                uint32_t off = ((m0 + mi * 16 + lrow) * ASTR + cb) * 2;
                ldsm_x4(ahi[mi][0], ahi[mi][1], ahi[mi][2], ahi[mi][3], sb + OAH + off);
                ldsm_x4(alo[mi][0], alo[mi][1], alo[mi][2], alo[mi][3], sb + OAL + off);
            }
            #pragma unroll
            for (int nj = 0; nj < 4; nj++) {
                uint32_t off = ((n0w + nj * 16 + lrow) * ASTR + cb) * 2;
                ldsm_x4(bh[nj][0], bh[nj][1], bh[nj][2], bh[nj][3], sb + OBH + off);
                ldsm_x4(bl[nj][0], bl[nj][1], bl[nj][2], bl[nj][3], sb + OBL + off);
            }
            #pragma unroll
            for (int mi = 0; mi < 2; mi++) {
                #pragma unroll
                for (int nj = 0; nj < 4; nj++) {
                    float* d0 = acc[mi][nj * 2];
                    mma_bf16(d0, ahi[mi], bh[nj][0], bh[nj][2]);
                    mma_bf16(d0, ahi[mi], bl[nj][0], bl[nj][2]);
                    mma_bf16(d0, alo[mi], bh[nj][0], bh[nj][2]);
                    float* d1 = acc[mi][nj * 2 + 1];
                    mma_bf16(d1, ahi[mi], bh[nj][1], bh[nj][3]);
                    mma_bf16(d1, ahi[mi], bl[nj][1], bl[nj][3]);
                    mma_bf16(d1, alo[mi], bh[nj][1], bh[nj][3]);
                }
            }
        }

        if (has_next) {
            store_A(stage ^ 1);
            CP_WAIT0();
            __syncthreads();
            stage ^= 1;
        }
    }

    const int grp = lane >> 2, qid = lane & 3;
    #pragma unroll
    for (int mi = 0; mi < 2; mi++) {
        #pragma unroll
        for (int nj = 0; nj < 8; nj++) {
            int row = blockIdx.y * 128 + m0 + mi * 16 + grp;
            int col = blockIdx.x * 128 + n0w + nj * 8 + qid * 2;
            float b0 = bias[col], b1 = bias[col + 1];
            *(float2*)(Cb + (size_t)row * ldc + col) =
                make_float2(acc[mi][nj][0] + b0, acc[mi][nj][1] + b1);
            *(float2*)(Cb + (size_t)(row + 8) * ldc + col) =
                make_float2(acc[mi][nj][2] + b0, acc[mi][nj][3] + b1);
        }
    }
}

// ============== GEMM variant 2: BOTH operands pre-split bf16, all cp.async =====
__global__ __launch_bounds__(256, 2) void hmma_gemm_ab_kernel(
    const __nv_bfloat16* __restrict__ Ahi, const __nv_bfloat16* __restrict__ Alo,
    size_t strideA,
    const __nv_bfloat16* __restrict__ Bhi, const __nv_bfloat16* __restrict__ Blo,
    size_t strideB,
    float* __restrict__ Cm, int ldc, size_t strideC,
    const float* __restrict__ bias, int K)
{
    extern __shared__ __align__(16) char smd[];
    const uint32_t sbase = smem_to_u32(smd);

    const int tid = threadIdx.x;
    const int wid = tid >> 5, lane = tid & 31;
    const int wm = wid & 3, wn = wid >> 2;
    const int m0 = wm * 32, n0w = wn * 64;

    const __nv_bfloat16* Ahb = Ahi + (size_t)blockIdx.z * strideA + (size_t)(blockIdx.y * 128) * K;
    const __nv_bfloat16* Alb = Alo + (size_t)blockIdx.z * strideA + (size_t)(blockIdx.y * 128) * K;
    const __nv_bfloat16* Bhb = Bhi + (size_t)blockIdx.z * strideB + (size_t)(blockIdx.x * 128) * K;
    const __nv_bfloat16* Blb = Blo + (size_t)blockIdx.z * strideB + (size_t)(blockIdx.x * 128) * K;
    float* Cb = Cm + (size_t)blockIdx.z * strideC;

    const int lrow = lane & 15;
    const int lcol = (lane >> 4) * 8;
    const int c0row = tid >> 1, c0seg = (tid & 1) * 2;

    float acc[2][8][4];
    #pragma unroll
    for (int mi = 0; mi < 2; mi++)
        #pragma unroll
        for (int n = 0; n < 8; n++)
            #pragma unroll
            for (int q = 0; q < 4; q++) acc[mi][n][q] = 0.f;

    auto cpasync_all = [&](int kt, int stg) {
        uint32_t dst = sbase + stg * STAGE_BYTES + c0row * (ASTR * 2) + c0seg * 16;
        const char* sah = (const char*)(Ahb + (size_t)c0row * K + kt) + c0seg * 16;
        const char* sal = (const char*)(Alb + (size_t)c0row * K + kt) + c0seg * 16;
        const char* sbh = (const char*)(Bhb + (size_t)c0row * K + kt) + c0seg * 16;
        const char* sbl = (const char*)(Blb + (size_t)c0row * K + kt) + c0seg * 16;
        CP_ASYNC16(dst + OAH, sah); CP_ASYNC16(dst + OAH + 16, sah + 16);
        CP_ASYNC16(dst + OAL, sal); CP_ASYNC16(dst + OAL + 16, sal + 16);
        CP_ASYNC16(dst + OBH, sbh); CP_ASYNC16(dst + OBH + 16, sbh + 16);
        CP_ASYNC16(dst + OBL, sbl); CP_ASYNC16(dst + OBL + 16, sbl + 16);
    };

    cpasync_all(0, 0);
    CP_COMMIT();
    CP_WAIT0();
    __syncthreads();

    int stage = 0;
    for (int kt = 0; kt < K; kt += 32) {
        const bool has_next = (kt + 32 < K);
        if (has_next) {
            cpasync_all(kt + 32, stage ^ 1);
            CP_COMMIT();
        }

        const uint32_t sb = sbase + stage * STAGE_BYTES;
        #pragma unroll
        for (int ks = 0; ks < 2; ks++) {
            const int cb = ks * 16 + lcol;
            uint32_t ahi[2][4], alo[2][4], bh[4][4], bl[4][4];
            #pragma unroll
            for (int mi = 0; mi < 2; mi++) {
                uint32_t off = ((m0 + mi * 16 + lrow) * ASTR + cb) * 2;
                ldsm_x4(ahi[mi][0], ahi[mi][1], ahi[mi][2], ahi[mi][3], sb + OAH + off);
                ldsm_x4(alo[mi][0], alo[mi][1], alo[mi][2], alo[mi][3], sb + OAL + off);
            }
            #pragma unroll
            for (int nj = 0; nj < 4; nj++) {
                uint32_t off = ((n0w + nj * 16 + lrow) * ASTR + cb) * 2;
                ldsm_x4(bh[nj][0], bh[nj][1], bh[nj][2], bh[nj][3], sb + OBH + off);
                ldsm_x4(bl[nj][0], bl[nj][1], bl[nj][2], bl[nj][3], sb + OBL + off);
            }
            #pragma unroll
            for (int mi = 0; mi < 2; mi++) {
                #pragma unroll
                for (int nj = 0; nj < 4; nj++) {
                    float* d0 = acc[mi][nj * 2];
                    mma_bf16(d0, ahi[mi], bh[nj][0], bh[nj][2]);
                    mma_bf16(d0, ahi[mi], bl[nj][0], bl[nj][2]);
                    mma_bf16(d0, alo[mi], bh[nj][0], bh[nj][2]);
                    float* d1 = acc[mi][nj * 2 + 1];
                    mma_bf16(d1, ahi[mi], bh[nj][1], bh[nj][3]);
                    mma_bf16(d1, ahi[mi], bl[nj][1], bl[nj][3]);
                    mma_bf16(d1, alo[mi], bh[nj][1], bh[nj][3]);
                }
            }
        }

        if (has_next) {
            CP_WAIT0();
            __syncthreads();
            stage ^= 1;
        }
    }

    const int grp = lane >> 2, qid = lane & 3;
    #pragma unroll
    for (int mi = 0; mi < 2; mi++) {
        #pragma unroll
        for (int nj = 0; nj < 8; nj++) {
            int row = blockIdx.y * 128 + m0 + mi * 16 + grp;
            int col = blockIdx.x * 128 + n0w + nj * 8 + qid * 2;
            float b0 = bias[col], b1 = bias[col + 1];
            *(float2*)(Cb + (size_t)row * ldc + col) =
                make_float2(acc[mi][nj][0] + b0, acc[mi][nj][1] + b1);
            *(float2*)(Cb + (size_t)(row + 8) * ldc + col) =
                make_float2(acc[mi][nj][2] + b0, acc[mi][nj][3] + b1);
        }
    }
}

// ---------------- prep: split W_in into transposed bf16 hi/lo ------------------
__global__ __launch_bounds__(256) void split_w_kernel(const float* __restrict__ W)
{
    int idx = blockIdx.x * 256 + threadIdx.x;   // k*256 + n
    int k = idx >> 8, n = idx & 255;
    float v = W[idx];
    __nv_bfloat16 h = __float2bfloat16_rn(v);
    g_Whi[(size_t)n * C_ + k] = h;
    g_Wlo[(size_t)n * C_ + k] = __float2bfloat16_rn(v - __bfloat162float(h));
}

// ---------------- K2: slice weights -> bf16 hi/lo only -------------------------
__global__ __launch_bounds__(256) void slicew_kernel(
    const float* __restrict__ Wslice, const float* __restrict__ bslice,
    const float* __restrict__ temp)
{
    __shared__ float Ws[D_ * G_];
    __shared__ float bs[G_];
    __shared__ float it[H_];
    int tid = threadIdx.x;
    #pragma unroll
    for (int i = 0; i < 8; i++) Ws[tid + i * 256] = Wslice[tid + i * 256];
    if (tid < G_) bs[tid] = bslice[tid];
    if (tid < H_) it[tid] = 1.f / temp[tid];
    __syncthreads();

    int gid = blockIdx.x * 256 + tid;
    int n = gid >> 3, h = gid & 7;

    float x[D_];
    const float4* xr = (const float4*)(g_tmp + (size_t)n * C_ + h * D_);
    #pragma unroll
    for (int i = 0; i < 8; i++) {
        float4 v = xr[i];
        x[4*i] = v.x; x[4*i+1] = v.y; x[4*i+2] = v.z; x[4*i+3] = v.w;
    }

    float2 lg[G_ / 2];
    const float2* bs2 = (const float2*)bs;
    #pragma unroll
    for (int j = 0; j < G_ / 2; j++) lg[j] = bs2[j];

    const float2* Ws2 = (const float2*)Ws;
    for (int d = 0; d < D_; d++) {
        float2 xv = make_float2(x[d], x[d]);
        #pragma unroll
        for (int j = 0; j < G_ / 2; j++) lg[j] = ffma2(xv, Ws2[d * (G_ / 2) + j], lg[j]);
    }

    float sc = it[h];
    float mx = -1e30f;
    #pragma unroll
    for (int j = 0; j < G_ / 2; j++) {
        lg[j].x *= sc; lg[j].y *= sc;
        mx = fmaxf(mx, fmaxf(lg[j].x, lg[j].y));
    }
    float sum = 0.f;
    #pragma unroll
    for (int j = 0; j < G_ / 2; j++) {
        lg[j].x = __expf(lg[j].x - mx);
        lg[j].y = __expf(lg[j].y - mx);
        sum += lg[j].x + lg[j].y;
    }
    float inv = 1.f / sum;

    size_t base = (size_t)n * (H_ * G_) + h * G_;
    uint2* dhi = (uint2*)(g_swhi + base);
    uint2* dlo = (uint2*)(g_swlo + base);
    #pragma unroll
    for (int j = 0; j < 16; j++) {
        float v0 = lg[2*j].x * inv, v1 = lg[2*j].y * inv;
        float v2 = lg[2*j+1].x * inv, v3 = lg[2*j+1].y * inv;
        __nv_bfloat162 h01 = __floats2bfloat162_rn(v0, v1);
        __nv_bfloat162 h23 = __floats2bfloat162_rn(v2, v3);
        dhi[j] = make_uint2(bits2(h01), bits2(h23));
        __nv_bfloat162 l01 = __floats2bfloat162_rn(v0 - __bfloat162float(h01.x),
                                                   v1 - __bfloat162float(h01.y));
        __nv_bfloat162 l23 = __floats2bfloat162_rn(v2 - __bfloat162float(h23.x),
                                                   v3 - __bfloat162float(h23.y));
        dlo[j] = make_uint2(bits2(l01), bits2(l23));
    }
}

// ---------------- K3: pooling as HMMA GEMM -------------------------------------
// per (pc, bh): out[g, d(+norm)] += sw[n,g]^T @ xext[n,d] over 512 k-rows.
// sw/x staged [n][*], transposed in-smem via ldmatrix + stmatrix.trans.
// smem layout (bytes):
#define P_S0SWH 0
#define P_S0SWL 9216
#define P_S0XH  18432
#define P_S0XL  23552
#define P_SWTH  28672
#define P_SWTL  37888
#define P_SXTH  47104
#define P_SXTL  54016
#define P_TOTAL 61440

__global__ __launch_bounds__(128) void pool_mma_kernel()
{
    extern __shared__ __align__(16) char psm[];
    const uint32_t sb = smem_to_u32(psm);

    const int tid = threadIdx.x, lane = tid & 31, w = tid >> 5;
    const int pc = blockIdx.x, bh = blockIdx.y;
    const int b = bh >> 3, h = bh & 7;
    const int lrow = lane & 15, lcol = (lane >> 4) * 8;
    const int r8 = lane >> 3, q8 = lane & 7;

    // init xT constant rows: row 32 = ones (norm), rows 33..47 = 0
    for (int i = tid; i < 16 * 64; i += 128) {
        int row = 32 + (i >> 6), n = i & 63;
        *(uint16_t*)(psm + P_SXTH + (row * 72 + n) * 2) = (row == 32) ? 0x3F80 : 0;
        *(uint16_t*)(psm + P_SXTL + (row * 72 + n) * 2) = 0;
    }
    __syncthreads();

    float acc[4][5][4];
    #pragma unroll
    for (int mi = 0; mi < 4; mi++)
        #pragma unroll
        for (int nj = 0; nj < 5; nj++)
            #pragma unroll
            for (int q = 0; q < 4; q++) acc[mi][nj][q] = 0.f;

    for (int sc = 0; sc < 8; sc++) {
        size_t gn = (size_t)b * T_ + pc * 512 + sc * 64;   // global row base

        // stage sw [64 n][64 g] hi/lo via cp.async
        #pragma unroll
        for (int i = 0; i < 4; i++) {
            int c = tid + i * 128;           // 0..511
            int row = c >> 3, seg = c & 7;
            const char* srch = (const char*)(g_swhi + (gn + row) * (H_ * G_) + h * G_) + seg * 16;
            const char* srcl = (const char*)(g_swlo + (gn + row) * (H_ * G_) + h * G_) + seg * 16;
            CP_ASYNC16(sb + P_S0SWH + row * 144 + seg * 16, srch);
            CP_ASYNC16(sb + P_S0SWL + row * 144 + seg * 16, srcl);
        }
        CP_COMMIT();

        // stage x [64 n][32 d] hi/lo (fp32 -> split bf16)
        if (tid < 64) {
            const float* xp = g_tmp + (gn + tid) * C_ + h * D_;
            uint32_t hu[16], lu[16];
            #pragma unroll
            for (int i = 0; i < 8; i++) {
                float4 v = ((const float4*)xp)[i];
                __nv_bfloat162 h0 = __floats2bfloat162_rn(v.x, v.y);
                __nv_bfloat162 h1 = __floats2bfloat162_rn(v.z, v.w);
                hu[2*i] = bits2(h0); hu[2*i+1] = bits2(h1);
                lu[2*i] = bits2(__floats2bfloat162_rn(v.x - __bfloat162float(h0.x),
                                                      v.y - __bfloat162float(h0.y)));
                lu[2*i+1] = bits2(__floats2bfloat162_rn(v.z - __bfloat162float(h1.x),
                                                        v.w - __bfloat162float(h1.y)));
            }
            #pragma unroll
            for (int i = 0; i < 4; i++) {
                *(uint4*)(psm + P_S0XH + tid * 80 + i * 16) =
                    make_uint4(hu[4*i], hu[4*i+1], hu[4*i+2], hu[4*i+3]);
                *(uint4*)(psm + P_S0XL + tid * 80 + i * 16) =
                    make_uint4(lu[4*i], lu[4*i+1], lu[4*i+2], lu[4*i+3]);
            }
        }
        CP_WAIT0();
        __syncthreads();

        // transpose sw: warp w owns g-block gbw = w*16
        {
            int gbw = w * 16;
            #pragma unroll
            for (int nb = 0; nb < 64; nb += 16) {
                uint32_t f0, f1, f2, f3;
                uint32_t dsty = sb + ((gbw + (r8 >> 1) * 8 + q8) * 72 + nb + (r8 & 1) * 8) * 2;
                ldsm_x4(f0, f1, f2, f3, sb + P_S0SWH + ((nb + lrow) * 72 + gbw + lcol) * 2);
                stsm_x4_t(dsty + P_SWTH, f0, f1, f2, f3);
                ldsm_x4(f0, f1, f2, f3, sb + P_S0SWL + ((nb + lrow) * 72 + gbw + lcol) * 2);
                stsm_x4_t(dsty + P_SWTL, f0, f1, f2, f3);
            }
        }
        // transpose x: warp w owns n-block nbw = w*16
        {
            int nbw = w * 16;
            #pragma unroll
            for (int db = 0; db < 32; db += 16) {
                uint32_t f0, f1, f2, f3;
                uint32_t dsty = sb + ((db + (r8 >> 1) * 8 + q8) * 72 + nbw + (r8 & 1) * 8) * 2;
                ldsm_x4(f0, f1, f2, f3, sb + P_S0XH + ((nbw + lrow) * 40 + db + lcol) * 2);
                stsm_x4_t(dsty + P_SXTH, f0, f1, f2, f3);
                ldsm_x4(f0, f1, f2, f3, sb + P_S0XL + ((nbw + lrow) * 40 + db + lcol) * 2);
                stsm_x4_t(dsty + P_SXTL, f0, f1, f2, f3);
            }
        }
        __syncthreads();

        // GEMM: warp w takes k-slice cb = w*16 (one k16 step)
        {
            int cb = w * 16;
            uint32_t bhh[3][4], bll[3][4];
            #pragma unroll
            for (int njt = 0; njt < 3; njt++) {
                uint32_t off = ((njt * 16 + lrow) * 72 + cb + lcol) * 2;
                ldsm_x4(bhh[njt][0], bhh[njt][1], bhh[njt][2], bhh[njt][3], sb + P_SXTH + off);
                ldsm_x4(bll[njt][0], bll[njt][1], bll[njt][2], bll[njt][3], sb + P_SXTL + off);
            }
            #pragma unroll
            for (int mi = 0; mi < 4; mi++) {
                uint32_t ah[4], al[4];
                uint32_t off = ((mi * 16 + lrow) * 72 + cb + lcol) * 2;
                ldsm_x4(ah[0], ah[1], ah[2], ah[3], sb + P_SWTH + off);
                ldsm_x4(al[0], al[1], al[2], al[3], sb + P_SWTL + off);
                #pragma unroll
                for (int nj = 0; nj < 5; nj++) {
                    int njt = nj >> 1, p = nj & 1;
                    float* d = acc[mi][nj];
                    mma_bf16(d, ah, bhh[njt][p], bhh[njt][p + 2]);
                    mma_bf16(d, ah, bll[njt][p], bll[njt][p + 2]);
                    mma_bf16(d, al, bhh[njt][p], bhh[njt][p + 2]);
                }
            }
        }
        __syncthreads();
    }

    // cross-warp reduction: red[w][64 g][40 n] fp32 (reuse smem)
    float* red = (float*)psm;
    const int grp = lane >> 2, qid = lane & 3;
    #pragma unroll
    for (int mi = 0; mi < 4; mi++) {
        #pragma unroll
        for (int nj = 0; nj < 5; nj++) {
            int g0 = mi * 16 + grp, nn = nj * 8 + qid * 2;
            red[(w * 64 + g0) * 40 + nn]       = acc[mi][nj][0];
            red[(w * 64 + g0) * 40 + nn + 1]   = acc[mi][nj][1];
            red[(w * 64 + g0 + 8) * 40 + nn]     = acc[mi][nj][2];
            red[(w * 64 + g0 + 8) * 40 + nn + 1] = acc[mi][nj][3];
        }
    }
    __syncthreads();

    for (int i = tid; i < 64 * 33; i += 128) {
        int g = i / 33, s = i - g * 33;
        float sum = red[g * 40 + s] + red[(64 + g) * 40 + s]
                  + red[(128 + g) * 40 + s] + red[(192 + g) * 40 + s];
        if (s < 32) g_part[((size_t)bh * NCH2 + pc) * (G_ * D_) + g * D_ + s] = sum;
        else        g_pnorm[((size_t)bh * NCH2 + pc) * G_ + g] = sum;
    }
}

// ------- K4a: reduce partials -> tokens -> qkv -> GxG attention -> g_os --------
__global__ __launch_bounds__(256) void attn_tiny_kernel(
    const float* __restrict__ Wq, const float* __restrict__ bq,
    const float* __restrict__ Wk, const float* __restrict__ bk,
    const float* __restrict__ Wv, const float* __restrict__ bv)
{
    __shared__ float tok[G_][D_ + 1];
    __shared__ float qs[G_][D_ + 1];
    __shared__ float ks[G_][D_ + 1];
    __shared__ float vs[G_][D_ + 1];
    __shared__ float norms[G_];

    int bh = blockIdx.x;
    int tid = threadIdx.x;

    if (tid < G_) {
        float s = 0.f;
        for (int ch = 0; ch < NCH2; ch++)
            s += g_pnorm[((size_t)bh * NCH2 + ch) * G_ + tid];
        norms[tid] = s + 1e-5f;
    }
    __syncthreads();

    #pragma unroll
    for (int i = 0; i < 8; i++) {
        int c = tid + i * 256;
        int g = c >> 5, d = c & 31;
        float s = 0.f;
        for (int ch = 0; ch < NCH2; ch++)
            s += g_part[((size_t)bh * NCH2 + ch) * (G_ * D_) + c];
        tok[g][d] = s / norms[g];
    }
    __syncthreads();

    #pragma unroll
    for (int i = 0; i < 8; i++) {
        int c = tid + i * 256;
        int g = c >> 5, d = c & 31;
        float aq = bq[d], ak = bk[d], av = bv[d];
        for (int e = 0; e < D_; e++) {
            float t = tok[g][e];
            aq += t * Wq[e * D_ + d];
            ak += t * Wk[e * D_ + d];
            av += t * Wv[e * D_ + d];
        }
        qs[g][d] = aq; ks[g][d] = ak; vs[g][d] = av;
    }
    __syncthreads();

    if (tid < G_) {
        float qr[D_];
        #pragma unroll
        for (int d = 0; d < D_; d++) qr[d] = qs[tid][d];
        float s[G_];
        float mx = -1e30f;
        #pragma unroll
        for (int j = 0; j < G_; j++) {
            float a = 0.f;
            #pragma unroll
            for (int d = 0; d < D_; d++) a += qr[d] * ks[j][d];
            a *= 0.17677669529663687f;
            s[j] = a; mx = fmaxf(mx, a);
        }
        float sum = 0.f;
        #pragma unroll
        for (int j = 0; j < G_; j++) { s[j] = __expf(s[j] - mx); sum += s[j]; }
        float inv = 1.f / sum;
        #pragma unroll
        for (int d = 0; d < D_; d++) {
            float a = 0.f;
            #pragma unroll
            for (int j = 0; j < G_; j++) a += s[j] * vs[j][d];
            g_os[(size_t)bh * (G_ * D_) + tid * D_ + d] = a * inv;
        }
    }
}

// ------- K4b: fold into transposed bf16 hi/lo M --------------------------------
__global__ __launch_bounds__(256) void fold_kernel(const float* __restrict__ Wout)
{
    __shared__ float os[G_][D_ + 1];
    __shared__ float Wt[D_][G_ + 1];
    int bh = blockIdx.y;
    int b = bh >> 3, h = bh & 7;
    int col0 = blockIdx.x * 64;
    int tid = threadIdx.x;

    #pragma unroll
    for (int i = 0; i < 8; i++) {
        int idx = tid + i * 256;
        os[idx >> 5][idx & 31] = g_os[(size_t)bh * (G_ * D_) + idx];
    }
    #pragma unroll
    for (int i = 0; i < 8; i++) {
        int idx = tid + i * 256;
        int d = idx >> 6, c = idx & 63;
        Wt[d][c] = Wout[(size_t)(h * D_ + d) * C_ + col0 + c];
    }
    __syncthreads();

    int c = tid & 63, g0 = tid >> 6;
    #pragma unroll
    for (int gi = 0; gi < 16; gi++) {
        int g = g0 * 16 + gi;
        float a = 0.f;
        #pragma unroll
        for (int d = 0; d < D_; d++) a += os[g][d] * Wt[d][c];
        __nv_bfloat16 hb = __float2bfloat16_rn(a);
        size_t o = ((size_t)b * C_ + col0 + c) * (size_t)(H_ * G_) + h * G_ + g;
        g_Mhi[o] = hb;
        g_Mlo[o] = __float2bfloat16_rn(a - __bfloat162float(hb));
    }
}

// ---------------- launch --------------------------------------------------------
extern "C" void kernel_launch(void* const* d_in, const int* in_sizes, int n_in,
                              void* d_out, int out_size)
{
    const float* x_q    = (const float*)d_in[0];
    const float* W_in   = (const float*)d_in[3];
    const float* b_in   = (const float*)d_in[4];
    const float* W_sl   = (const float*)d_in[5];
    const float* b_sl   = (const float*)d_in[6];
    const float* temp   = (const float*)d_in[7];
    const float* W_q    = (const float*)d_in[8];
    const float* b_q    = (const float*)d_in[9];
    const float* W_k    = (const float*)d_in[10];
    const float* b_k    = (const float*)d_in[11];
    const float* W_v    = (const float*)d_in[12];
    const float* b_v    = (const float*)d_in[13];
    const float* W_out  = (const float*)d_in[14];
    const float* b_out  = (const float*)d_in[15];
    float* out = (float*)d_out;

    float *tmp_p;
    __nv_bfloat16 *whi_p, *wlo_p, *mhi_p, *mlo_p, *shi_p, *slo_p;
    cudaGetSymbolAddress((void**)&tmp_p, g_tmp);
    cudaGetSymbolAddress((void**)&whi_p, g_Whi);
    cudaGetSymbolAddress((void**)&wlo_p, g_Wlo);
    cudaGetSymbolAddress((void**)&mhi_p, g_Mhi);
    cudaGetSymbolAddress((void**)&mlo_p, g_Mlo);
    cudaGetSymbolAddress((void**)&shi_p, g_swhi);
    cudaGetSymbolAddress((void**)&slo_p, g_swlo);

    static int smem_set = 0;
    if (!smem_set) {
        cudaFuncSetAttribute(hmma_gemm_kernel,
                             cudaFuncAttributeMaxDynamicSharedMemorySize, GEMM_SMEM);
        cudaFuncSetAttribute(hmma_gemm_ab_kernel,
                             cudaFuncAttributeMaxDynamicSharedMemorySize, GEMM_SMEM);
        cudaFuncSetAttribute(pool_mma_kernel,
                             cudaFuncAttributeMaxDynamicSharedMemorySize, P_TOTAL);
        smem_set = 1;
    }

    // prep: split W_in
    split_w_kernel<<<C_ * C_ / 256, 256>>>(W_in);

    // K1: tmp = x_q @ W_in + b_in
    hmma_gemm_kernel<<<dim3(C_/128, N_/128, 1), 256, GEMM_SMEM>>>(
        x_q, C_, 0, whi_p, wlo_p, 0, tmp_p, C_, 0, b_in, C_);

    // K2: slice softmax -> bf16 hi/lo only
    slicew_kernel<<<(N_ * H_) / 256, 256>>>(W_sl, b_sl, temp);

    // K3: pooling as tensor-core GEMM (16 k-chunks x 64 bh)
    pool_mma_kernel<<<dim3(NCH2, B_ * H_), 128, P_TOTAL>>>();

    // K4a: reduce + tiny attention
    attn_tiny_kernel<<<B_ * H_, 256>>>(W_q, b_q, W_k, b_k, W_v, b_v);

    // K4b: fold W_out into pre-split M
    fold_kernel<<<dim3(4, B_ * H_), 256>>>(W_out);

    // K5: out[b] = SW[b] @ M[b] + b_out
    hmma_gemm_ab_kernel<<<dim3(C_/128, T_/128, B_), 256, GEMM_SMEM>>>(
        shi_p, slo_p, (size_t)T_ * (H_ * G_),
        mhi_p, mlo_p, (size_t)C_ * (H_ * G_),
        out, C_, (size_t)T_ * C_,
        b_out, H_ * G_);
}